// round 1
// baseline (speedup 1.0000x reference)
#include <cuda_runtime.h>
#include <math.h>

// ---------------------------------------------------------------------------
// DecoderBlock (DiT-style): AdaLN -> MHA -> residual -> AdaLN -> FFN -> residual
// B=2, S=2048 (T=4096 tokens), D=1024, H=16, d=64, D_COND=512, FF=4096, fp32.
// ---------------------------------------------------------------------------

#define T_TOK 4096

// Scratch (device globals; allocation-free per harness rules)
__device__ float g_sc  [T_TOK * 512];    // silu(cond)
__device__ float g_gb1 [T_TOK * 2048];   // gamma|beta 1
__device__ float g_gb2 [T_TOK * 2048];   // gamma|beta 2
__device__ float g_h   [T_TOK * 1024];   // adaln1 out
__device__ float g_qkv [T_TOK * 3072];   // qkv
__device__ float g_attn[T_TOK * 1024];   // attention out (B,S,D)
__device__ float g_x2  [T_TOK * 1024];   // after attn residual
__device__ float g_h2  [T_TOK * 1024];   // adaln2 out
__device__ float g_ff  [T_TOK * 4096];   // ffn mid

enum { EPI_NONE = 0, EPI_BIAS = 1, EPI_BIAS_GELU = 2, EPI_RES = 3, EPI_BIAS_RES = 4 };

__device__ __forceinline__ float gelu_exact(float v) {
    return 0.5f * v * (1.0f + erff(v * 0.70710678118654752440f));
}

// ---------------------------------------------------------------------------
// SGEMM: C(MxN) = A(MxK) @ B(KxN) [+bias][+gelu][+res]
// 128x128 tile, BK=8, 256 threads, 8x8 per-thread microtile.
// Requires M%128==0, N%128==0, K%8==0 (true for all shapes here).
// ---------------------------------------------------------------------------
template <int EPI>
__global__ __launch_bounds__(256) void sgemm128(
    const float* __restrict__ A, const float* __restrict__ B, float* __restrict__ C,
    int M, int N, int K,
    const float* __restrict__ bias, const float* __restrict__ res)
{
    __shared__ float As[8][128];   // transposed A tile: As[k][m]
    __shared__ float Bs[8][128];   // Bs[k][n]

    const int tid = threadIdx.x;
    const int tx  = tid & 15;
    const int ty  = tid >> 4;
    const int bx  = blockIdx.x;    // N tile
    const int by  = blockIdx.y;    // M tile

    const int arow = tid >> 1;           // 0..127
    const int ac4  = (tid & 1) * 4;      // 0 or 4
    const int brow = tid >> 5;           // 0..7
    const int bc4  = (tid & 31) * 4;     // 0..124

    const float* Aptr = A + (size_t)(by * 128 + arow) * K + ac4;
    const float* Bptr = B + (size_t)brow * N + bx * 128 + bc4;

    float acc[8][8];
    #pragma unroll
    for (int i = 0; i < 8; i++)
        #pragma unroll
        for (int j = 0; j < 8; j++) acc[i][j] = 0.0f;

    for (int kt = 0; kt < K; kt += 8) {
        float4 av = *reinterpret_cast<const float4*>(Aptr + kt);
        float4 bv = *reinterpret_cast<const float4*>(Bptr + (size_t)kt * N);
        As[ac4 + 0][arow] = av.x;
        As[ac4 + 1][arow] = av.y;
        As[ac4 + 2][arow] = av.z;
        As[ac4 + 3][arow] = av.w;
        *reinterpret_cast<float4*>(&Bs[brow][bc4]) = bv;
        __syncthreads();

        #pragma unroll
        for (int k = 0; k < 8; k++) {
            float4 a0 = *reinterpret_cast<const float4*>(&As[k][ty * 4]);
            float4 a1 = *reinterpret_cast<const float4*>(&As[k][64 + ty * 4]);
            float4 b0 = *reinterpret_cast<const float4*>(&Bs[k][tx * 4]);
            float4 b1 = *reinterpret_cast<const float4*>(&Bs[k][64 + tx * 4]);
            float ar[8] = {a0.x, a0.y, a0.z, a0.w, a1.x, a1.y, a1.z, a1.w};
            float br[8] = {b0.x, b0.y, b0.z, b0.w, b1.x, b1.y, b1.z, b1.w};
            #pragma unroll
            for (int i = 0; i < 8; i++)
                #pragma unroll
                for (int j = 0; j < 8; j++)
                    acc[i][j] = fmaf(ar[i], br[j], acc[i][j]);
        }
        __syncthreads();
    }

    float bcol[8];
    if (EPI == EPI_BIAS || EPI == EPI_BIAS_GELU || EPI == EPI_BIAS_RES) {
        #pragma unroll
        for (int j = 0; j < 8; j++) {
            int c = bx * 128 + ((j < 4) ? (tx * 4 + j) : (64 + tx * 4 + (j - 4)));
            bcol[j] = bias[c];
        }
    }

    #pragma unroll
    for (int i = 0; i < 8; i++) {
        int r = by * 128 + ((i < 4) ? (ty * 4 + i) : (64 + ty * 4 + (i - 4)));
        size_t rowbase = (size_t)r * N + (size_t)bx * 128;
        float v[8];
        #pragma unroll
        for (int j = 0; j < 8; j++) {
            float val = acc[i][j];
            if (EPI == EPI_BIAS || EPI == EPI_BIAS_GELU || EPI == EPI_BIAS_RES)
                val += bcol[j];
            if (EPI == EPI_BIAS_GELU)
                val = gelu_exact(val);
            if (EPI == EPI_RES || EPI == EPI_BIAS_RES) {
                int cc = (j < 4) ? (tx * 4 + j) : (64 + tx * 4 + (j - 4));
                val += res[rowbase + cc];
            }
            v[j] = val;
        }
        *reinterpret_cast<float4*>(&C[rowbase + tx * 4])      = make_float4(v[0], v[1], v[2], v[3]);
        *reinterpret_cast<float4*>(&C[rowbase + 64 + tx * 4]) = make_float4(v[4], v[5], v[6], v[7]);
    }
}

// ---------------------------------------------------------------------------
// SiLU elementwise: out = x * sigmoid(x)
// ---------------------------------------------------------------------------
__global__ void silu_kernel(const float* __restrict__ in, float* __restrict__ out, int n)
{
    int i = blockIdx.x * blockDim.x + threadIdx.x;
    if (i < n) {
        float v = in[i];
        out[i] = v / (1.0f + __expf(-v));
    }
}

// ---------------------------------------------------------------------------
// Block reduce (256 threads = 8 warps)
// ---------------------------------------------------------------------------
__device__ __forceinline__ float blockReduceSum256(float v)
{
    __shared__ float sh[8];
    int lane = threadIdx.x & 31;
    int wid  = threadIdx.x >> 5;
    #pragma unroll
    for (int o = 16; o; o >>= 1) v += __shfl_xor_sync(0xffffffffu, v, o);
    __syncthreads();                 // protect sh from previous use
    if (lane == 0) sh[wid] = v;
    __syncthreads();
    float s = 0.0f;
    #pragma unroll
    for (int i = 0; i < 8; i++) s += sh[i];
    return s;
}

// ---------------------------------------------------------------------------
// AdaLN: per-row (D=1024) LayerNorm(no affine) then (1+gamma)*xn + beta
// gb row layout: [gamma(1024) | beta(1024)]
// ---------------------------------------------------------------------------
__global__ __launch_bounds__(256) void adaln_kernel(
    const float* __restrict__ x, const float* __restrict__ gb, float* __restrict__ h)
{
    int row = blockIdx.x;
    int t   = threadIdx.x;
    const float* xr = x + (size_t)row * 1024;

    float4 v = *reinterpret_cast<const float4*>(xr + t * 4);
    float s = v.x + v.y + v.z + v.w;
    s = blockReduceSum256(s);
    float mu = s * (1.0f / 1024.0f);

    float dx = v.x - mu, dy = v.y - mu, dz = v.z - mu, dw = v.w - mu;
    float s2 = dx * dx + dy * dy + dz * dz + dw * dw;
    s2 = blockReduceSum256(s2);
    float rstd = rsqrtf(s2 * (1.0f / 1024.0f) + 1e-5f);

    const float* gbr = gb + (size_t)row * 2048;
    float4 g = *reinterpret_cast<const float4*>(gbr + t * 4);
    float4 b = *reinterpret_cast<const float4*>(gbr + 1024 + t * 4);

    float4 o;
    o.x = dx * rstd * (1.0f + g.x) + b.x;
    o.y = dy * rstd * (1.0f + g.y) + b.y;
    o.z = dz * rstd * (1.0f + g.z) + b.z;
    o.w = dw * rstd * (1.0f + g.w) + b.w;
    *reinterpret_cast<float4*>(h + (size_t)row * 1024 + t * 4) = o;
}

// ---------------------------------------------------------------------------
// Flash attention, fp32. One block per (q-tile of 64, b*h). 256 threads.
// qkv layout: [token][3*1024], q at h*64, k at 1024+h*64, v at 2048+h*64.
// ---------------------------------------------------------------------------
#define ATTN_SMEM_FLOATS (4160 * 3 + 4096)
#define ATTN_SMEM_BYTES  (ATTN_SMEM_FLOATS * 4)

__global__ __launch_bounds__(256) void attn_kernel(
    const float* __restrict__ qkv, float* __restrict__ out)
{
    extern __shared__ float smem[];
    float (*Qt)[65] = (float(*)[65])(smem);          // [d][q-row], padded
    float (*Kt)[65] = (float(*)[65])(smem + 4160);   // [d][k-row], padded
    float (*Pt)[65] = (float(*)[65])(smem + 8320);   // [k-row][q-row], padded
    float (*Vs)[64] = (float(*)[64])(smem + 12480);  // [k-row][d]

    const int qt  = blockIdx.x;        // 0..31
    const int bh  = blockIdx.y;        // 0..31
    const int b   = bh >> 4;
    const int hd  = bh & 15;
    const int tok0 = b * 2048;
    const int qb = hd * 64, kb = 1024 + hd * 64, vb = 2048 + hd * 64;

    const int tid = threadIdx.x;
    const int tx  = tid & 15;
    const int ty  = tid >> 4;

    // Load Q tile transposed: Qt[d][r]
    for (int i = tid; i < 1024; i += 256) {
        int r  = i >> 4;
        int c4 = (i & 15) * 4;
        float4 v = *reinterpret_cast<const float4*>(
            &qkv[(size_t)(tok0 + qt * 64 + r) * 3072 + qb + c4]);
        Qt[c4 + 0][r] = v.x;
        Qt[c4 + 1][r] = v.y;
        Qt[c4 + 2][r] = v.z;
        Qt[c4 + 3][r] = v.w;
    }

    float m[4], l[4], o[4][4];
    #pragma unroll
    for (int i = 0; i < 4; i++) {
        m[i] = -1e30f;
        l[i] = 0.0f;
        #pragma unroll
        for (int j = 0; j < 4; j++) o[i][j] = 0.0f;
    }

    for (int kt2 = 0; kt2 < 32; kt2++) {
        // Load K tile transposed + V tile direct
        for (int i = tid; i < 1024; i += 256) {
            int r  = i >> 4;
            int c4 = (i & 15) * 4;
            size_t base = (size_t)(tok0 + kt2 * 64 + r) * 3072;
            float4 kv = *reinterpret_cast<const float4*>(&qkv[base + kb + c4]);
            Kt[c4 + 0][r] = kv.x;
            Kt[c4 + 1][r] = kv.y;
            Kt[c4 + 2][r] = kv.z;
            Kt[c4 + 3][r] = kv.w;
            float4 vv = *reinterpret_cast<const float4*>(&qkv[base + vb + c4]);
            *reinterpret_cast<float4*>(&Vs[r][c4]) = vv;
        }
        __syncthreads();

        // S = Q @ K^T   (thread owns S[4ty+i][4tx+j])
        float s[4][4];
        #pragma unroll
        for (int i = 0; i < 4; i++)
            #pragma unroll
            for (int j = 0; j < 4; j++) s[i][j] = 0.0f;

        for (int d = 0; d < 64; d++) {
            float qa[4], ka[4];
            #pragma unroll
            for (int i = 0; i < 4; i++) qa[i] = Qt[d][4 * ty + i];
            #pragma unroll
            for (int j = 0; j < 4; j++) ka[j] = Kt[d][4 * tx + j];
            #pragma unroll
            for (int i = 0; i < 4; i++)
                #pragma unroll
                for (int j = 0; j < 4; j++)
                    s[i][j] = fmaf(qa[i], ka[j], s[i][j]);
        }

        // Online softmax (row reductions across the 16-lane tx group)
        #pragma unroll
        for (int i = 0; i < 4; i++) {
            float rm = -1e30f;
            #pragma unroll
            for (int j = 0; j < 4; j++) {
                s[i][j] *= 0.125f;                 // 1/sqrt(64)
                rm = fmaxf(rm, s[i][j]);
            }
            #pragma unroll
            for (int off = 8; off >= 1; off >>= 1)
                rm = fmaxf(rm, __shfl_xor_sync(0xffffffffu, rm, off));
            float mn    = fmaxf(m[i], rm);
            float alpha = __expf(m[i] - mn);
            float rs = 0.0f;
            #pragma unroll
            for (int j = 0; j < 4; j++) {
                s[i][j] = __expf(s[i][j] - mn);
                rs += s[i][j];
            }
            #pragma unroll
            for (int off = 8; off >= 1; off >>= 1)
                rs += __shfl_xor_sync(0xffffffffu, rs, off);
            l[i] = l[i] * alpha + rs;
            m[i] = mn;
            #pragma unroll
            for (int j = 0; j < 4; j++) o[i][j] *= alpha;
        }

        // Stage P transposed: Pt[k-col][q-row]
        #pragma unroll
        for (int i = 0; i < 4; i++)
            #pragma unroll
            for (int j = 0; j < 4; j++)
                Pt[4 * tx + j][4 * ty + i] = s[i][j];
        __syncthreads();

        // O += P @ V
        for (int k = 0; k < 64; k++) {
            float pa[4], va[4];
            #pragma unroll
            for (int i = 0; i < 4; i++) pa[i] = Pt[k][4 * ty + i];
            #pragma unroll
            for (int j = 0; j < 4; j++) va[j] = Vs[k][4 * tx + j];
            #pragma unroll
            for (int i = 0; i < 4; i++)
                #pragma unroll
                for (int j = 0; j < 4; j++)
                    o[i][j] = fmaf(pa[i], va[j], o[i][j]);
        }
        __syncthreads();
    }

    // Write O / l  -> out[(b,s),(h*64+d)]
    #pragma unroll
    for (int i = 0; i < 4; i++) {
        float inv = 1.0f / l[i];
        float4 ov = make_float4(o[i][0] * inv, o[i][1] * inv, o[i][2] * inv, o[i][3] * inv);
        size_t idx = (size_t)(tok0 + qt * 64 + 4 * ty + i) * 1024 + hd * 64 + 4 * tx;
        *reinterpret_cast<float4*>(&out[idx]) = ov;
    }
}

// ---------------------------------------------------------------------------
// Launch
// ---------------------------------------------------------------------------
extern "C" void kernel_launch(void* const* d_in, const int* in_sizes, int n_in,
                              void* d_out, int out_size)
{
    const float* x        = (const float*)d_in[0];
    const float* cond     = (const float*)d_in[1];
    const float* p1_w     = (const float*)d_in[2];
    const float* p1_b     = (const float*)d_in[3];
    const float* qkv_w    = (const float*)d_in[4];
    const float* attn_o_w = (const float*)d_in[5];
    const float* p2_w     = (const float*)d_in[6];
    const float* p2_b     = (const float*)d_in[7];
    const float* ffn_w1   = (const float*)d_in[8];
    const float* ffn_b1   = (const float*)d_in[9];
    const float* ffn_w2   = (const float*)d_in[10];
    const float* ffn_b2   = (const float*)d_in[11];
    float* out = (float*)d_out;

    float *sc, *gb1, *gb2, *h, *qkvp, *attn, *x2, *h2, *ff;
    cudaGetSymbolAddress((void**)&sc,   g_sc);
    cudaGetSymbolAddress((void**)&gb1,  g_gb1);
    cudaGetSymbolAddress((void**)&gb2,  g_gb2);
    cudaGetSymbolAddress((void**)&h,    g_h);
    cudaGetSymbolAddress((void**)&qkvp, g_qkv);
    cudaGetSymbolAddress((void**)&attn, g_attn);
    cudaGetSymbolAddress((void**)&x2,   g_x2);
    cudaGetSymbolAddress((void**)&h2,   g_h2);
    cudaGetSymbolAddress((void**)&ff,   g_ff);

    cudaFuncSetAttribute(attn_kernel, cudaFuncAttributeMaxDynamicSharedMemorySize,
                         ATTN_SMEM_BYTES);

    // 1) sc = silu(cond)
    silu_kernel<<<(T_TOK * 512 + 255) / 256, 256>>>(cond, sc, T_TOK * 512);

    // 2) gb1 = sc @ p1_w + p1_b   (4096x512 @ 512x2048)
    sgemm128<EPI_BIAS><<<dim3(16, 32), 256>>>(sc, p1_w, gb1, T_TOK, 2048, 512, p1_b, nullptr);

    // gb2 = sc @ p2_w + p2_b (independent; overlap-friendly)
    sgemm128<EPI_BIAS><<<dim3(16, 32), 256>>>(sc, p2_w, gb2, T_TOK, 2048, 512, p2_b, nullptr);

    // 3) h = adaln(x, gb1)
    adaln_kernel<<<T_TOK, 256>>>(x, gb1, h);

    // 4) qkv = h @ qkv_w  (4096x1024 @ 1024x3072)
    sgemm128<EPI_NONE><<<dim3(24, 32), 256>>>(h, qkv_w, qkvp, T_TOK, 3072, 1024, nullptr, nullptr);

    // 5) attention
    attn_kernel<<<dim3(32, 32), 256, ATTN_SMEM_BYTES>>>(qkvp, attn);

    // 6) x2 = x + attn @ attn_out_w  (4096x1024 @ 1024x1024)
    sgemm128<EPI_RES><<<dim3(8, 32), 256>>>(attn, attn_o_w, x2, T_TOK, 1024, 1024, nullptr, x);

    // 7) h2 = adaln(x2, gb2)
    adaln_kernel<<<T_TOK, 256>>>(x2, gb2, h2);

    // 8) ff = gelu(h2 @ ffn_w1 + b1)  (4096x1024 @ 1024x4096)
    sgemm128<EPI_BIAS_GELU><<<dim3(32, 32), 256>>>(h2, ffn_w1, ff, T_TOK, 4096, 1024, ffn_b1, nullptr);

    // 9) out = x2 + ff @ ffn_w2 + b2  (4096x4096 @ 4096x1024)
    sgemm128<EPI_BIAS_RES><<<dim3(8, 32), 256>>>(ff, ffn_w2, out, T_TOK, 1024, 4096, ffn_b2, x2);
}

// round 2
// speedup vs baseline: 1.7731x; 1.7731x over previous
#include <cuda_runtime.h>
#include <math.h>
#include <stdint.h>

// ---------------------------------------------------------------------------
// DecoderBlock (DiT-style): AdaLN -> MHA -> residual -> AdaLN -> FFN -> residual
// B=2, S=2048 (T=4096 tokens), D=1024, H=16, d=64, D_COND=512, FF=4096, fp32.
// GEMMs on tf32 tensor cores (m16n8k8 HMMA), attention fp32 w/ vector LDS.
// ---------------------------------------------------------------------------

#define T_TOK 4096

__device__ float g_sc  [T_TOK * 512];
__device__ float g_gb1 [T_TOK * 2048];
__device__ float g_gb2 [T_TOK * 2048];
__device__ float g_h   [T_TOK * 1024];
__device__ float g_qkv [T_TOK * 3072];
__device__ float g_attn[T_TOK * 1024];
__device__ float g_x2  [T_TOK * 1024];
__device__ float g_h2  [T_TOK * 1024];
__device__ float g_ff  [T_TOK * 4096];

enum { EPI_NONE = 0, EPI_BIAS = 1, EPI_BIAS_GELU = 2, EPI_RES = 3, EPI_BIAS_RES = 4 };

__device__ __forceinline__ float gelu_exact(float v) {
    return 0.5f * v * (1.0f + erff(v * 0.70710678118654752440f));
}

__device__ __forceinline__ float to_tf32(float x) {
    uint32_t u;
    asm("cvt.rna.tf32.f32 %0, %1;" : "=r"(u) : "f"(x));
    return __uint_as_float(u);
}

__device__ __forceinline__ void mma_tf32(float* c,
    uint32_t a0, uint32_t a1, uint32_t a2, uint32_t a3, uint32_t b0, uint32_t b1)
{
    asm volatile(
        "mma.sync.aligned.m16n8k8.row.col.f32.tf32.tf32.f32 "
        "{%0,%1,%2,%3},{%4,%5,%6,%7},{%8,%9},{%0,%1,%2,%3};\n"
        : "+f"(c[0]), "+f"(c[1]), "+f"(c[2]), "+f"(c[3])
        : "r"(a0), "r"(a1), "r"(a2), "r"(a3), "r"(b0), "r"(b1));
}

// ---------------------------------------------------------------------------
// tf32 GEMM: C(MxN) = A(MxK) @ B(KxN) [+bias][+gelu][+res]
// 128x128 tile, BK=16, 256 threads (8 warps), warp tile 64x32 (4x4 m16n8k8).
// Requires M%128==0, N%128==0, K%16==0.
// SMEM stride 136 (=8 mod 32): fragment LDS banks 8*gc+gr -> conflict free.
// ---------------------------------------------------------------------------
template <int EPI>
__global__ __launch_bounds__(256, 2) void tf32gemm(
    const float* __restrict__ A, const float* __restrict__ B, float* __restrict__ C,
    int M, int N, int K,
    const float* __restrict__ bias, const float* __restrict__ res)
{
    __shared__ float As[16][136];   // [k][m]
    __shared__ float Bs[16][136];   // [k][n]

    const int tid  = threadIdx.x;
    const int bx   = blockIdx.x;    // N tile
    const int by   = blockIdx.y;    // M tile
    const int lane = tid & 31;
    const int wid  = tid >> 5;
    const int wm   = (wid >> 2) * 64;   // warp M offset in tile
    const int wn   = (wid & 3) * 32;    // warp N offset in tile
    const int gr   = lane >> 2;         // 0..7  (groupID)
    const int gc   = lane & 3;          // 0..3  (threadID_in_group)

    // staging indices
    const int ar = tid >> 1;            // 0..127 (A row)
    const int ac = (tid & 1) * 8;       // 0 or 8 (A col base)
    const int br = tid >> 4;            // 0..15  (B row)
    const int bc = (tid & 15) * 8;      // 0..120 (B col base)

    const float* Ag = A + (size_t)(by * 128 + ar) * K + ac;
    const float* Bg = B + (size_t)br * N + (size_t)bx * 128 + bc;

    float acc[4][4][4];
    #pragma unroll
    for (int mi = 0; mi < 4; mi++)
        #pragma unroll
        for (int ni = 0; ni < 4; ni++)
            #pragma unroll
            for (int q = 0; q < 4; q++) acc[mi][ni][q] = 0.0f;

    const int nk = K >> 4;

    float4 a0v = *reinterpret_cast<const float4*>(Ag);
    float4 a1v = *reinterpret_cast<const float4*>(Ag + 4);
    float4 b0v = *reinterpret_cast<const float4*>(Bg);
    float4 b1v = *reinterpret_cast<const float4*>(Bg + 4);

    for (int kt = 0; kt < nk; kt++) {
        // stage (convert to tf32 once here)
        As[ac + 0][ar] = to_tf32(a0v.x);
        As[ac + 1][ar] = to_tf32(a0v.y);
        As[ac + 2][ar] = to_tf32(a0v.z);
        As[ac + 3][ar] = to_tf32(a0v.w);
        As[ac + 4][ar] = to_tf32(a1v.x);
        As[ac + 5][ar] = to_tf32(a1v.y);
        As[ac + 6][ar] = to_tf32(a1v.z);
        As[ac + 7][ar] = to_tf32(a1v.w);
        float4 tb0 = make_float4(to_tf32(b0v.x), to_tf32(b0v.y), to_tf32(b0v.z), to_tf32(b0v.w));
        float4 tb1 = make_float4(to_tf32(b1v.x), to_tf32(b1v.y), to_tf32(b1v.z), to_tf32(b1v.w));
        *reinterpret_cast<float4*>(&Bs[br][bc])     = tb0;
        *reinterpret_cast<float4*>(&Bs[br][bc + 4]) = tb1;
        __syncthreads();

        if (kt + 1 < nk) {
            const float* Ag2 = Ag + (kt + 1) * 16;
            const float* Bg2 = Bg + (size_t)(kt + 1) * 16 * N;
            a0v = *reinterpret_cast<const float4*>(Ag2);
            a1v = *reinterpret_cast<const float4*>(Ag2 + 4);
            b0v = *reinterpret_cast<const float4*>(Bg2);
            b1v = *reinterpret_cast<const float4*>(Bg2 + 4);
        }

        #pragma unroll
        for (int k8 = 0; k8 < 16; k8 += 8) {
            uint32_t af[4][4], bf[4][2];
            #pragma unroll
            for (int mi = 0; mi < 4; mi++) {
                af[mi][0] = __float_as_uint(As[k8 + gc    ][wm + mi * 16 + gr]);
                af[mi][1] = __float_as_uint(As[k8 + gc    ][wm + mi * 16 + gr + 8]);
                af[mi][2] = __float_as_uint(As[k8 + gc + 4][wm + mi * 16 + gr]);
                af[mi][3] = __float_as_uint(As[k8 + gc + 4][wm + mi * 16 + gr + 8]);
            }
            #pragma unroll
            for (int ni = 0; ni < 4; ni++) {
                bf[ni][0] = __float_as_uint(Bs[k8 + gc    ][wn + ni * 8 + gr]);
                bf[ni][1] = __float_as_uint(Bs[k8 + gc + 4][wn + ni * 8 + gr]);
            }
            #pragma unroll
            for (int mi = 0; mi < 4; mi++)
                #pragma unroll
                for (int ni = 0; ni < 4; ni++)
                    mma_tf32(acc[mi][ni], af[mi][0], af[mi][1], af[mi][2], af[mi][3],
                             bf[ni][0], bf[ni][1]);
        }
        __syncthreads();
    }

    // Epilogue. C frag: c0:(gr, gc*2) c1:(gr, gc*2+1) c2:(gr+8, gc*2) c3:(gr+8, gc*2+1)
    #pragma unroll
    for (int mi = 0; mi < 4; mi++) {
        #pragma unroll
        for (int half = 0; half < 2; half++) {
            int r = by * 128 + wm + mi * 16 + gr + half * 8;
            size_t rowbase = (size_t)r * N + (size_t)bx * 128;
            #pragma unroll
            for (int ni = 0; ni < 4; ni++) {
                int c = wn + ni * 8 + gc * 2;
                float v0 = acc[mi][ni][half * 2 + 0];
                float v1 = acc[mi][ni][half * 2 + 1];
                if (EPI == EPI_BIAS || EPI == EPI_BIAS_GELU || EPI == EPI_BIAS_RES) {
                    v0 += bias[bx * 128 + c];
                    v1 += bias[bx * 128 + c + 1];
                }
                if (EPI == EPI_BIAS_GELU) { v0 = gelu_exact(v0); v1 = gelu_exact(v1); }
                if (EPI == EPI_RES || EPI == EPI_BIAS_RES) {
                    v0 += res[rowbase + c];
                    v1 += res[rowbase + c + 1];
                }
                *reinterpret_cast<float2*>(&C[rowbase + c]) = make_float2(v0, v1);
            }
        }
    }
}

// ---------------------------------------------------------------------------
// SiLU elementwise
// ---------------------------------------------------------------------------
__global__ void silu_kernel(const float* __restrict__ in, float* __restrict__ out, int n)
{
    int i = blockIdx.x * blockDim.x + threadIdx.x;
    if (i < n) {
        float v = in[i];
        out[i] = v / (1.0f + __expf(-v));
    }
}

// ---------------------------------------------------------------------------
// Block reduce (256 threads = 8 warps)
// ---------------------------------------------------------------------------
__device__ __forceinline__ float blockReduceSum256(float v)
{
    __shared__ float sh[8];
    int lane = threadIdx.x & 31;
    int wid  = threadIdx.x >> 5;
    #pragma unroll
    for (int o = 16; o; o >>= 1) v += __shfl_xor_sync(0xffffffffu, v, o);
    __syncthreads();
    if (lane == 0) sh[wid] = v;
    __syncthreads();
    float s = 0.0f;
    #pragma unroll
    for (int i = 0; i < 8; i++) s += sh[i];
    return s;
}

// ---------------------------------------------------------------------------
// AdaLN
// ---------------------------------------------------------------------------
__global__ __launch_bounds__(256) void adaln_kernel(
    const float* __restrict__ x, const float* __restrict__ gb, float* __restrict__ h)
{
    int row = blockIdx.x;
    int t   = threadIdx.x;
    const float* xr = x + (size_t)row * 1024;

    float4 v = *reinterpret_cast<const float4*>(xr + t * 4);
    float s = v.x + v.y + v.z + v.w;
    s = blockReduceSum256(s);
    float mu = s * (1.0f / 1024.0f);

    float dx = v.x - mu, dy = v.y - mu, dz = v.z - mu, dw = v.w - mu;
    float s2 = dx * dx + dy * dy + dz * dz + dw * dw;
    s2 = blockReduceSum256(s2);
    float rstd = rsqrtf(s2 * (1.0f / 1024.0f) + 1e-5f);

    const float* gbr = gb + (size_t)row * 2048;
    float4 g = *reinterpret_cast<const float4*>(gbr + t * 4);
    float4 b = *reinterpret_cast<const float4*>(gbr + 1024 + t * 4);

    float4 o;
    o.x = dx * rstd * (1.0f + g.x) + b.x;
    o.y = dy * rstd * (1.0f + g.y) + b.y;
    o.z = dz * rstd * (1.0f + g.z) + b.z;
    o.w = dw * rstd * (1.0f + g.w) + b.w;
    *reinterpret_cast<float4*>(h + (size_t)row * 1024 + t * 4) = o;
}

// ---------------------------------------------------------------------------
// Flash attention, fp32, vectorized LDS. One block per (q-tile 64, b*h).
// Padding 68 so rows are 16B aligned -> float4 LDS/STS.
// ---------------------------------------------------------------------------
#define ATTN_SMEM_FLOATS (4352 * 3 + 4096)
#define ATTN_SMEM_BYTES  (ATTN_SMEM_FLOATS * 4)

__global__ __launch_bounds__(256) void attn_kernel(
    const float* __restrict__ qkv, float* __restrict__ out)
{
    extern __shared__ float smem[];
    float (*Qt)[68] = (float(*)[68])(smem);           // [d][q-row]
    float (*Kt)[68] = (float(*)[68])(smem + 4352);    // [d][k-row]
    float (*Pt)[68] = (float(*)[68])(smem + 8704);    // [k-row][q-row]
    float (*Vs)[64] = (float(*)[64])(smem + 13056);   // [k-row][d]

    const int qt  = blockIdx.x;
    const int bh  = blockIdx.y;
    const int b   = bh >> 4;
    const int hd  = bh & 15;
    const int tok0 = b * 2048;
    const int qb = hd * 64, kb = 1024 + hd * 64, vb = 2048 + hd * 64;

    const int tid = threadIdx.x;
    const int tx  = tid & 15;
    const int ty  = tid >> 4;

    for (int i = tid; i < 1024; i += 256) {
        int r  = i >> 4;
        int c4 = (i & 15) * 4;
        float4 v = *reinterpret_cast<const float4*>(
            &qkv[(size_t)(tok0 + qt * 64 + r) * 3072 + qb + c4]);
        Qt[c4 + 0][r] = v.x;
        Qt[c4 + 1][r] = v.y;
        Qt[c4 + 2][r] = v.z;
        Qt[c4 + 3][r] = v.w;
    }

    float m[4], l[4], o[4][4];
    #pragma unroll
    for (int i = 0; i < 4; i++) {
        m[i] = -1e30f;
        l[i] = 0.0f;
        #pragma unroll
        for (int j = 0; j < 4; j++) o[i][j] = 0.0f;
    }

    for (int kt2 = 0; kt2 < 32; kt2++) {
        for (int i = tid; i < 1024; i += 256) {
            int r  = i >> 4;
            int c4 = (i & 15) * 4;
            size_t base = (size_t)(tok0 + kt2 * 64 + r) * 3072;
            float4 kv = *reinterpret_cast<const float4*>(&qkv[base + kb + c4]);
            Kt[c4 + 0][r] = kv.x;
            Kt[c4 + 1][r] = kv.y;
            Kt[c4 + 2][r] = kv.z;
            Kt[c4 + 3][r] = kv.w;
            float4 vv = *reinterpret_cast<const float4*>(&qkv[base + vb + c4]);
            *reinterpret_cast<float4*>(&Vs[r][c4]) = vv;
        }
        __syncthreads();

        float s[4][4];
        #pragma unroll
        for (int i = 0; i < 4; i++)
            #pragma unroll
            for (int j = 0; j < 4; j++) s[i][j] = 0.0f;

        #pragma unroll 8
        for (int d = 0; d < 64; d++) {
            float4 qa = *reinterpret_cast<const float4*>(&Qt[d][4 * ty]);
            float4 ka = *reinterpret_cast<const float4*>(&Kt[d][4 * tx]);
            float ar[4] = {qa.x, qa.y, qa.z, qa.w};
            float br[4] = {ka.x, ka.y, ka.z, ka.w};
            #pragma unroll
            for (int i = 0; i < 4; i++)
                #pragma unroll
                for (int j = 0; j < 4; j++)
                    s[i][j] = fmaf(ar[i], br[j], s[i][j]);
        }

        #pragma unroll
        for (int i = 0; i < 4; i++) {
            float rm = -1e30f;
            #pragma unroll
            for (int j = 0; j < 4; j++) {
                s[i][j] *= 0.125f;
                rm = fmaxf(rm, s[i][j]);
            }
            #pragma unroll
            for (int off = 8; off >= 1; off >>= 1)
                rm = fmaxf(rm, __shfl_xor_sync(0xffffffffu, rm, off));
            float mn    = fmaxf(m[i], rm);
            float alpha = __expf(m[i] - mn);
            float rs = 0.0f;
            #pragma unroll
            for (int j = 0; j < 4; j++) {
                s[i][j] = __expf(s[i][j] - mn);
                rs += s[i][j];
            }
            #pragma unroll
            for (int off = 8; off >= 1; off >>= 1)
                rs += __shfl_xor_sync(0xffffffffu, rs, off);
            l[i] = l[i] * alpha + rs;
            m[i] = mn;
            #pragma unroll
            for (int j = 0; j < 4; j++) o[i][j] *= alpha;
        }

        #pragma unroll
        for (int j = 0; j < 4; j++)
            *reinterpret_cast<float4*>(&Pt[4 * tx + j][4 * ty]) =
                make_float4(s[0][j], s[1][j], s[2][j], s[3][j]);
        __syncthreads();

        #pragma unroll 8
        for (int k = 0; k < 64; k++) {
            float4 pa = *reinterpret_cast<const float4*>(&Pt[k][4 * ty]);
            float4 va = *reinterpret_cast<const float4*>(&Vs[k][4 * tx]);
            float ar[4] = {pa.x, pa.y, pa.z, pa.w};
            float br[4] = {va.x, va.y, va.z, va.w};
            #pragma unroll
            for (int i = 0; i < 4; i++)
                #pragma unroll
                for (int j = 0; j < 4; j++)
                    o[i][j] = fmaf(ar[i], br[j], o[i][j]);
        }
        __syncthreads();
    }

    #pragma unroll
    for (int i = 0; i < 4; i++) {
        float inv = 1.0f / l[i];
        float4 ov = make_float4(o[i][0] * inv, o[i][1] * inv, o[i][2] * inv, o[i][3] * inv);
        size_t idx = (size_t)(tok0 + qt * 64 + 4 * ty + i) * 1024 + hd * 64 + 4 * tx;
        *reinterpret_cast<float4*>(&out[idx]) = ov;
    }
}

// ---------------------------------------------------------------------------
// Launch
// ---------------------------------------------------------------------------
extern "C" void kernel_launch(void* const* d_in, const int* in_sizes, int n_in,
                              void* d_out, int out_size)
{
    const float* x        = (const float*)d_in[0];
    const float* cond     = (const float*)d_in[1];
    const float* p1_w     = (const float*)d_in[2];
    const float* p1_b     = (const float*)d_in[3];
    const float* qkv_w    = (const float*)d_in[4];
    const float* attn_o_w = (const float*)d_in[5];
    const float* p2_w     = (const float*)d_in[6];
    const float* p2_b     = (const float*)d_in[7];
    const float* ffn_w1   = (const float*)d_in[8];
    const float* ffn_b1   = (const float*)d_in[9];
    const float* ffn_w2   = (const float*)d_in[10];
    const float* ffn_b2   = (const float*)d_in[11];
    float* out = (float*)d_out;

    float *sc, *gb1, *gb2, *h, *qkvp, *attn, *x2, *h2, *ff;
    cudaGetSymbolAddress((void**)&sc,   g_sc);
    cudaGetSymbolAddress((void**)&gb1,  g_gb1);
    cudaGetSymbolAddress((void**)&gb2,  g_gb2);
    cudaGetSymbolAddress((void**)&h,    g_h);
    cudaGetSymbolAddress((void**)&qkvp, g_qkv);
    cudaGetSymbolAddress((void**)&attn, g_attn);
    cudaGetSymbolAddress((void**)&x2,   g_x2);
    cudaGetSymbolAddress((void**)&h2,   g_h2);
    cudaGetSymbolAddress((void**)&ff,   g_ff);

    cudaFuncSetAttribute(attn_kernel, cudaFuncAttributeMaxDynamicSharedMemorySize,
                         ATTN_SMEM_BYTES);

    // 1) sc = silu(cond)
    silu_kernel<<<(T_TOK * 512 + 255) / 256, 256>>>(cond, sc, T_TOK * 512);

    // 2) gb1 = sc @ p1_w + p1_b   (4096x512 @ 512x2048)
    tf32gemm<EPI_BIAS><<<dim3(16, 32), 256>>>(sc, p1_w, gb1, T_TOK, 2048, 512, p1_b, nullptr);

    // gb2 = sc @ p2_w + p2_b
    tf32gemm<EPI_BIAS><<<dim3(16, 32), 256>>>(sc, p2_w, gb2, T_TOK, 2048, 512, p2_b, nullptr);

    // 3) h = adaln(x, gb1)
    adaln_kernel<<<T_TOK, 256>>>(x, gb1, h);

    // 4) qkv = h @ qkv_w  (4096x1024 @ 1024x3072)
    tf32gemm<EPI_NONE><<<dim3(24, 32), 256>>>(h, qkv_w, qkvp, T_TOK, 3072, 1024, nullptr, nullptr);

    // 5) attention
    attn_kernel<<<dim3(32, 32), 256, ATTN_SMEM_BYTES>>>(qkvp, attn);

    // 6) x2 = x + attn @ attn_out_w  (4096x1024 @ 1024x1024)
    tf32gemm<EPI_RES><<<dim3(8, 32), 256>>>(attn, attn_o_w, x2, T_TOK, 1024, 1024, nullptr, x);

    // 7) h2 = adaln(x2, gb2)
    adaln_kernel<<<T_TOK, 256>>>(x2, gb2, h2);

    // 8) ff = gelu(h2 @ ffn_w1 + b1)  (4096x1024 @ 1024x4096)
    tf32gemm<EPI_BIAS_GELU><<<dim3(32, 32), 256>>>(h2, ffn_w1, ff, T_TOK, 4096, 1024, ffn_b1, nullptr);

    // 9) out = x2 + ff @ ffn_w2 + b2  (4096x4096 @ 4096x1024)
    tf32gemm<EPI_BIAS_RES><<<dim3(8, 32), 256>>>(ff, ffn_w2, out, T_TOK, 1024, 4096, ffn_b2, x2);
}

// round 3
// speedup vs baseline: 2.6475x; 1.4932x over previous
#include <cuda_runtime.h>
#include <math.h>
#include <stdint.h>

// ---------------------------------------------------------------------------
// DecoderBlock (DiT-style): AdaLN -> MHA -> residual -> AdaLN -> FFN -> residual
// B=2, S=2048 (T=4096 tokens), D=1024, H=16, d=64, D_COND=512, FF=4096, fp32.
// GEMMs + attention on tf32 tensor cores (m16n8k8 HMMA).
// ---------------------------------------------------------------------------

#define T_TOK 4096

__device__ float g_sc  [T_TOK * 512];
__device__ float g_gb1 [T_TOK * 2048];
__device__ float g_gb2 [T_TOK * 2048];
__device__ float g_h   [T_TOK * 1024];
__device__ float g_qkv [T_TOK * 3072];
__device__ float g_attn[T_TOK * 1024];
__device__ float g_x2  [T_TOK * 1024];
__device__ float g_h2  [T_TOK * 1024];
__device__ float g_ff  [T_TOK * 4096];

enum { EPI_NONE = 0, EPI_BIAS = 1, EPI_BIAS_GELU = 2, EPI_RES = 3, EPI_BIAS_RES = 4 };

__device__ __forceinline__ float gelu_exact(float v) {
    return 0.5f * v * (1.0f + erff(v * 0.70710678118654752440f));
}

__device__ __forceinline__ float to_tf32(float x) {
    uint32_t u;
    asm("cvt.rna.tf32.f32 %0, %1;" : "=r"(u) : "f"(x));
    return __uint_as_float(u);
}

__device__ __forceinline__ void mma_tf32(float* c,
    uint32_t a0, uint32_t a1, uint32_t a2, uint32_t a3, uint32_t b0, uint32_t b1)
{
    asm volatile(
        "mma.sync.aligned.m16n8k8.row.col.f32.tf32.tf32.f32 "
        "{%0,%1,%2,%3},{%4,%5,%6,%7},{%8,%9},{%0,%1,%2,%3};\n"
        : "+f"(c[0]), "+f"(c[1]), "+f"(c[2]), "+f"(c[3])
        : "r"(a0), "r"(a1), "r"(a2), "r"(a3), "r"(b0), "r"(b1));
}

// ---------------------------------------------------------------------------
// tf32 GEMM: C(MxN) = A(MxK) @ B(KxN) [+bias][+gelu][+res]
// 128x128 tile, BK=16, 256 threads (8 warps), warp tile 64x32 (4x4 m16n8k8).
// Double-buffered smem (dynamic), one __syncthreads per k-tile.
// ---------------------------------------------------------------------------
#define GEMM_SMEM_BYTES (2 * 2 * 16 * 136 * 4)

template <int EPI>
__global__ __launch_bounds__(256, 2) void tf32gemm(
    const float* __restrict__ A, const float* __restrict__ B, float* __restrict__ C,
    int M, int N, int K,
    const float* __restrict__ bias, const float* __restrict__ res)
{
    extern __shared__ float sm[];
    float (*As)[16][136] = (float(*)[16][136])(sm);               // [buf][k][m]
    float (*Bs)[16][136] = (float(*)[16][136])(sm + 2 * 16 * 136);// [buf][k][n]

    const int tid  = threadIdx.x;
    const int bx   = blockIdx.x;
    const int by   = blockIdx.y;
    const int lane = tid & 31;
    const int wid  = tid >> 5;
    const int wm   = (wid >> 2) * 64;
    const int wn   = (wid & 3) * 32;
    const int gr   = lane >> 2;
    const int gc   = lane & 3;

    const int ar = tid >> 1;
    const int ac = (tid & 1) * 8;
    const int br = tid >> 4;
    const int bc = (tid & 15) * 8;

    const float* Ag = A + (size_t)(by * 128 + ar) * K + ac;
    const float* Bg = B + (size_t)br * N + (size_t)bx * 128 + bc;

    float acc[4][4][4];
    #pragma unroll
    for (int mi = 0; mi < 4; mi++)
        #pragma unroll
        for (int ni = 0; ni < 4; ni++)
            #pragma unroll
            for (int q = 0; q < 4; q++) acc[mi][ni][q] = 0.0f;

    const int nk = K >> 4;

    float4 a0v = *reinterpret_cast<const float4*>(Ag);
    float4 a1v = *reinterpret_cast<const float4*>(Ag + 4);
    float4 b0v = *reinterpret_cast<const float4*>(Bg);
    float4 b1v = *reinterpret_cast<const float4*>(Bg + 4);

    for (int kt = 0; kt < nk; kt++) {
        const int buf = kt & 1;
        As[buf][ac + 0][ar] = to_tf32(a0v.x);
        As[buf][ac + 1][ar] = to_tf32(a0v.y);
        As[buf][ac + 2][ar] = to_tf32(a0v.z);
        As[buf][ac + 3][ar] = to_tf32(a0v.w);
        As[buf][ac + 4][ar] = to_tf32(a1v.x);
        As[buf][ac + 5][ar] = to_tf32(a1v.y);
        As[buf][ac + 6][ar] = to_tf32(a1v.z);
        As[buf][ac + 7][ar] = to_tf32(a1v.w);
        float4 tb0 = make_float4(to_tf32(b0v.x), to_tf32(b0v.y), to_tf32(b0v.z), to_tf32(b0v.w));
        float4 tb1 = make_float4(to_tf32(b1v.x), to_tf32(b1v.y), to_tf32(b1v.z), to_tf32(b1v.w));
        *reinterpret_cast<float4*>(&Bs[buf][br][bc])     = tb0;
        *reinterpret_cast<float4*>(&Bs[buf][br][bc + 4]) = tb1;
        __syncthreads();

        if (kt + 1 < nk) {
            const float* Ag2 = Ag + (kt + 1) * 16;
            const float* Bg2 = Bg + (size_t)(kt + 1) * 16 * N;
            a0v = *reinterpret_cast<const float4*>(Ag2);
            a1v = *reinterpret_cast<const float4*>(Ag2 + 4);
            b0v = *reinterpret_cast<const float4*>(Bg2);
            b1v = *reinterpret_cast<const float4*>(Bg2 + 4);
        }

        #pragma unroll
        for (int k8 = 0; k8 < 16; k8 += 8) {
            uint32_t af[4][4], bf[4][2];
            #pragma unroll
            for (int mi = 0; mi < 4; mi++) {
                af[mi][0] = __float_as_uint(As[buf][k8 + gc    ][wm + mi * 16 + gr]);
                af[mi][1] = __float_as_uint(As[buf][k8 + gc    ][wm + mi * 16 + gr + 8]);
                af[mi][2] = __float_as_uint(As[buf][k8 + gc + 4][wm + mi * 16 + gr]);
                af[mi][3] = __float_as_uint(As[buf][k8 + gc + 4][wm + mi * 16 + gr + 8]);
            }
            #pragma unroll
            for (int ni = 0; ni < 4; ni++) {
                bf[ni][0] = __float_as_uint(Bs[buf][k8 + gc    ][wn + ni * 8 + gr]);
                bf[ni][1] = __float_as_uint(Bs[buf][k8 + gc + 4][wn + ni * 8 + gr]);
            }
            #pragma unroll
            for (int mi = 0; mi < 4; mi++)
                #pragma unroll
                for (int ni = 0; ni < 4; ni++)
                    mma_tf32(acc[mi][ni], af[mi][0], af[mi][1], af[mi][2], af[mi][3],
                             bf[ni][0], bf[ni][1]);
        }
    }

    #pragma unroll
    for (int mi = 0; mi < 4; mi++) {
        #pragma unroll
        for (int half = 0; half < 2; half++) {
            int r = by * 128 + wm + mi * 16 + gr + half * 8;
            size_t rowbase = (size_t)r * N + (size_t)bx * 128;
            #pragma unroll
            for (int ni = 0; ni < 4; ni++) {
                int c = wn + ni * 8 + gc * 2;
                float v0 = acc[mi][ni][half * 2 + 0];
                float v1 = acc[mi][ni][half * 2 + 1];
                if (EPI == EPI_BIAS || EPI == EPI_BIAS_GELU || EPI == EPI_BIAS_RES) {
                    v0 += bias[bx * 128 + c];
                    v1 += bias[bx * 128 + c + 1];
                }
                if (EPI == EPI_BIAS_GELU) { v0 = gelu_exact(v0); v1 = gelu_exact(v1); }
                if (EPI == EPI_RES || EPI == EPI_BIAS_RES) {
                    v0 += res[rowbase + c];
                    v1 += res[rowbase + c + 1];
                }
                *reinterpret_cast<float2*>(&C[rowbase + c]) = make_float2(v0, v1);
            }
        }
    }
}

// ---------------------------------------------------------------------------
// SiLU elementwise
// ---------------------------------------------------------------------------
__global__ void silu_kernel(const float* __restrict__ in, float* __restrict__ out, int n)
{
    int i = blockIdx.x * blockDim.x + threadIdx.x;
    if (i < n) {
        float v = in[i];
        out[i] = v / (1.0f + __expf(-v));
    }
}

// ---------------------------------------------------------------------------
// Block reduce (256 threads = 8 warps)
// ---------------------------------------------------------------------------
__device__ __forceinline__ float blockReduceSum256(float v)
{
    __shared__ float sh[8];
    int lane = threadIdx.x & 31;
    int wid  = threadIdx.x >> 5;
    #pragma unroll
    for (int o = 16; o; o >>= 1) v += __shfl_xor_sync(0xffffffffu, v, o);
    __syncthreads();
    if (lane == 0) sh[wid] = v;
    __syncthreads();
    float s = 0.0f;
    #pragma unroll
    for (int i = 0; i < 8; i++) s += sh[i];
    return s;
}

// ---------------------------------------------------------------------------
// AdaLN
// ---------------------------------------------------------------------------
__global__ __launch_bounds__(256) void adaln_kernel(
    const float* __restrict__ x, const float* __restrict__ gb, float* __restrict__ h)
{
    int row = blockIdx.x;
    int t   = threadIdx.x;
    const float* xr = x + (size_t)row * 1024;

    float4 v = *reinterpret_cast<const float4*>(xr + t * 4);
    float s = v.x + v.y + v.z + v.w;
    s = blockReduceSum256(s);
    float mu = s * (1.0f / 1024.0f);

    float dx = v.x - mu, dy = v.y - mu, dz = v.z - mu, dw = v.w - mu;
    float s2 = dx * dx + dy * dy + dz * dz + dw * dw;
    s2 = blockReduceSum256(s2);
    float rstd = rsqrtf(s2 * (1.0f / 1024.0f) + 1e-5f);

    const float* gbr = gb + (size_t)row * 2048;
    float4 g = *reinterpret_cast<const float4*>(gbr + t * 4);
    float4 b = *reinterpret_cast<const float4*>(gbr + 1024 + t * 4);

    float4 o;
    o.x = dx * rstd * (1.0f + g.x) + b.x;
    o.y = dy * rstd * (1.0f + g.y) + b.y;
    o.z = dz * rstd * (1.0f + g.z) + b.z;
    o.w = dw * rstd * (1.0f + g.w) + b.w;
    *reinterpret_cast<float4*>(h + (size_t)row * 1024 + t * 4) = o;
}

// ---------------------------------------------------------------------------
// Tensor-core flash attention (tf32). Q-tile 128, KV-tile 64, 8 warps.
// Warp w owns q rows [16w,16w+16) and the full 64 kv / 64 d columns.
// Strides: Qs/Ks/Ps 68 (frag LDS conflict-free), Vt 69 (worst 2-way).
// ---------------------------------------------------------------------------
#define QS_STRIDE 68
#define VT_STRIDE 69
#define ATTN_SMEM_FLOATS (128 * 68 + 64 * 68 + 64 * 69 + 128 * 68)
#define ATTN_SMEM_BYTES  (ATTN_SMEM_FLOATS * 4)

__global__ __launch_bounds__(256) void attn_kernel(
    const float* __restrict__ qkv, float* __restrict__ out)
{
    extern __shared__ float sm[];
    float (*Qs)[QS_STRIDE] = (float(*)[QS_STRIDE])(sm);                         // [128][68] q rows x d
    float (*Ks)[QS_STRIDE] = (float(*)[QS_STRIDE])(sm + 128 * 68);              // [64][68]  kv rows x d
    float (*Vt)[VT_STRIDE] = (float(*)[VT_STRIDE])(sm + 128 * 68 + 64 * 68);    // [64][69]  d rows x kv
    float (*Ps)[QS_STRIDE] = (float(*)[QS_STRIDE])(sm + 128 * 68 + 64 * 68 + 64 * 69); // [128][68]

    const int qt  = blockIdx.x;     // 0..15 (q tile of 128)
    const int bh  = blockIdx.y;     // 0..31
    const int b   = bh >> 4;
    const int hd  = bh & 15;
    const int tok0 = b * 2048;
    const int qb = hd * 64, kb = 1024 + hd * 64, vb = 2048 + hd * 64;

    const int tid  = threadIdx.x;
    const int lane = tid & 31;
    const int wid  = tid >> 5;
    const int wm   = wid * 16;
    const int gr   = lane >> 2;
    const int gc   = lane & 3;

    // loader indices: 16 rows x (16 lanes * float4)
    const int lr = tid >> 4;            // 0..15
    const int lc = (tid & 15) * 4;      // 0..60

    // ---- load Q (once), scaled by 1/sqrt(d)=0.125, tf32 ----
    #pragma unroll
    for (int s = 0; s < 8; s++) {
        int r = lr + s * 16;
        float4 v = *reinterpret_cast<const float4*>(
            &qkv[(size_t)(tok0 + qt * 128 + r) * 3072 + qb + lc]);
        Qs[r][lc + 0] = to_tf32(0.125f * v.x);
        Qs[r][lc + 1] = to_tf32(0.125f * v.y);
        Qs[r][lc + 2] = to_tf32(0.125f * v.z);
        Qs[r][lc + 3] = to_tf32(0.125f * v.w);
    }

    // ---- prefetch KV tile 0 into regs ----
    float4 kr4[4], vr4[4];
    #pragma unroll
    for (int s = 0; s < 4; s++) {
        size_t base = (size_t)(tok0 + lr + s * 16) * 3072;
        kr4[s] = *reinterpret_cast<const float4*>(&qkv[base + kb + lc]);
        vr4[s] = *reinterpret_cast<const float4*>(&qkv[base + vb + lc]);
    }

    float m0 = -1e30f, m1 = -1e30f, l0 = 0.0f, l1 = 0.0f;
    float o[8][4];
    #pragma unroll
    for (int nt = 0; nt < 8; nt++)
        #pragma unroll
        for (int q = 0; q < 4; q++) o[nt][q] = 0.0f;

    for (int kt = 0; kt < 32; kt++) {
        // ---- stage K (row-major) and V (transposed), tf32 ----
        #pragma unroll
        for (int s = 0; s < 4; s++) {
            int r = lr + s * 16;
            Ks[r][lc + 0] = to_tf32(kr4[s].x);
            Ks[r][lc + 1] = to_tf32(kr4[s].y);
            Ks[r][lc + 2] = to_tf32(kr4[s].z);
            Ks[r][lc + 3] = to_tf32(kr4[s].w);
            Vt[lc + 0][r] = to_tf32(vr4[s].x);
            Vt[lc + 1][r] = to_tf32(vr4[s].y);
            Vt[lc + 2][r] = to_tf32(vr4[s].z);
            Vt[lc + 3][r] = to_tf32(vr4[s].w);
        }
        __syncthreads();

        // prefetch next tile (latency hidden behind the MMAs below)
        if (kt + 1 < 32) {
            #pragma unroll
            for (int s = 0; s < 4; s++) {
                size_t base = (size_t)(tok0 + (kt + 1) * 64 + lr + s * 16) * 3072;
                kr4[s] = *reinterpret_cast<const float4*>(&qkv[base + kb + lc]);
                vr4[s] = *reinterpret_cast<const float4*>(&qkv[base + vb + lc]);
            }
        }

        // ---- S = Q @ K^T ----
        float sacc[8][4];
        #pragma unroll
        for (int nt = 0; nt < 8; nt++)
            #pragma unroll
            for (int q = 0; q < 4; q++) sacc[nt][q] = 0.0f;

        #pragma unroll
        for (int k8 = 0; k8 < 64; k8 += 8) {
            uint32_t a0 = __float_as_uint(Qs[wm + gr    ][k8 + gc]);
            uint32_t a1 = __float_as_uint(Qs[wm + gr + 8][k8 + gc]);
            uint32_t a2 = __float_as_uint(Qs[wm + gr    ][k8 + gc + 4]);
            uint32_t a3 = __float_as_uint(Qs[wm + gr + 8][k8 + gc + 4]);
            #pragma unroll
            for (int nt = 0; nt < 8; nt++) {
                uint32_t b0 = __float_as_uint(Ks[nt * 8 + gr][k8 + gc]);
                uint32_t b1 = __float_as_uint(Ks[nt * 8 + gr][k8 + gc + 4]);
                mma_tf32(sacc[nt], a0, a1, a2, a3, b0, b1);
            }
        }

        // ---- online softmax (rows gr and gr+8; 4 lanes/row -> shfl 1,2) ----
        float rm0 = -1e30f, rm1 = -1e30f;
        #pragma unroll
        for (int nt = 0; nt < 8; nt++) {
            rm0 = fmaxf(rm0, fmaxf(sacc[nt][0], sacc[nt][1]));
            rm1 = fmaxf(rm1, fmaxf(sacc[nt][2], sacc[nt][3]));
        }
        rm0 = fmaxf(rm0, __shfl_xor_sync(0xffffffffu, rm0, 1));
        rm0 = fmaxf(rm0, __shfl_xor_sync(0xffffffffu, rm0, 2));
        rm1 = fmaxf(rm1, __shfl_xor_sync(0xffffffffu, rm1, 1));
        rm1 = fmaxf(rm1, __shfl_xor_sync(0xffffffffu, rm1, 2));

        float mn0 = fmaxf(m0, rm0);
        float mn1 = fmaxf(m1, rm1);
        float al0 = __expf(m0 - mn0);
        float al1 = __expf(m1 - mn1);
        m0 = mn0; m1 = mn1;

        float sum0 = 0.0f, sum1 = 0.0f;
        #pragma unroll
        for (int nt = 0; nt < 8; nt++) {
            float p0 = __expf(sacc[nt][0] - mn0);
            float p1 = __expf(sacc[nt][1] - mn0);
            float p2 = __expf(sacc[nt][2] - mn1);
            float p3 = __expf(sacc[nt][3] - mn1);
            sum0 += p0 + p1;
            sum1 += p2 + p3;
            *reinterpret_cast<float2*>(&Ps[wm + gr    ][nt * 8 + 2 * gc]) =
                make_float2(to_tf32(p0), to_tf32(p1));
            *reinterpret_cast<float2*>(&Ps[wm + gr + 8][nt * 8 + 2 * gc]) =
                make_float2(to_tf32(p2), to_tf32(p3));
        }
        sum0 += __shfl_xor_sync(0xffffffffu, sum0, 1);
        sum0 += __shfl_xor_sync(0xffffffffu, sum0, 2);
        sum1 += __shfl_xor_sync(0xffffffffu, sum1, 1);
        sum1 += __shfl_xor_sync(0xffffffffu, sum1, 2);
        l0 = l0 * al0 + sum0;
        l1 = l1 * al1 + sum1;

        #pragma unroll
        for (int nt = 0; nt < 8; nt++) {
            o[nt][0] *= al0; o[nt][1] *= al0;
            o[nt][2] *= al1; o[nt][3] *= al1;
        }
        __syncwarp();   // Ps written (C-layout) -> read (A-layout) within warp

        // ---- O += P @ V ----
        #pragma unroll
        for (int k8 = 0; k8 < 64; k8 += 8) {
            uint32_t a0 = __float_as_uint(Ps[wm + gr    ][k8 + gc]);
            uint32_t a1 = __float_as_uint(Ps[wm + gr + 8][k8 + gc]);
            uint32_t a2 = __float_as_uint(Ps[wm + gr    ][k8 + gc + 4]);
            uint32_t a3 = __float_as_uint(Ps[wm + gr + 8][k8 + gc + 4]);
            #pragma unroll
            for (int nt = 0; nt < 8; nt++) {
                uint32_t b0 = __float_as_uint(Vt[nt * 8 + gr][k8 + gc]);
                uint32_t b1 = __float_as_uint(Vt[nt * 8 + gr][k8 + gc + 4]);
                mma_tf32(o[nt], a0, a1, a2, a3, b0, b1);
            }
        }
        __syncthreads();  // Ks/Vt consumed; safe to overwrite next iter
    }

    // ---- epilogue: O / l -> out[token][hd*64 + col] ----
    float inv0 = 1.0f / l0;
    float inv1 = 1.0f / l1;
    int t0 = tok0 + qt * 128 + wm + gr;
    int t1 = t0 + 8;
    #pragma unroll
    for (int nt = 0; nt < 8; nt++) {
        int col = hd * 64 + nt * 8 + 2 * gc;
        *reinterpret_cast<float2*>(&out[(size_t)t0 * 1024 + col]) =
            make_float2(o[nt][0] * inv0, o[nt][1] * inv0);
        *reinterpret_cast<float2*>(&out[(size_t)t1 * 1024 + col]) =
            make_float2(o[nt][2] * inv1, o[nt][3] * inv1);
    }
}

// ---------------------------------------------------------------------------
// Launch
// ---------------------------------------------------------------------------
extern "C" void kernel_launch(void* const* d_in, const int* in_sizes, int n_in,
                              void* d_out, int out_size)
{
    const float* x        = (const float*)d_in[0];
    const float* cond     = (const float*)d_in[1];
    const float* p1_w     = (const float*)d_in[2];
    const float* p1_b     = (const float*)d_in[3];
    const float* qkv_w    = (const float*)d_in[4];
    const float* attn_o_w = (const float*)d_in[5];
    const float* p2_w     = (const float*)d_in[6];
    const float* p2_b     = (const float*)d_in[7];
    const float* ffn_w1   = (const float*)d_in[8];
    const float* ffn_b1   = (const float*)d_in[9];
    const float* ffn_w2   = (const float*)d_in[10];
    const float* ffn_b2   = (const float*)d_in[11];
    float* out = (float*)d_out;

    float *sc, *gb1, *gb2, *h, *qkvp, *attn, *x2, *h2, *ff;
    cudaGetSymbolAddress((void**)&sc,   g_sc);
    cudaGetSymbolAddress((void**)&gb1,  g_gb1);
    cudaGetSymbolAddress((void**)&gb2,  g_gb2);
    cudaGetSymbolAddress((void**)&h,    g_h);
    cudaGetSymbolAddress((void**)&qkvp, g_qkv);
    cudaGetSymbolAddress((void**)&attn, g_attn);
    cudaGetSymbolAddress((void**)&x2,   g_x2);
    cudaGetSymbolAddress((void**)&h2,   g_h2);
    cudaGetSymbolAddress((void**)&ff,   g_ff);

    static int attr_done = 0;
    if (!attr_done) {
        cudaFuncSetAttribute(attn_kernel, cudaFuncAttributeMaxDynamicSharedMemorySize, ATTN_SMEM_BYTES);
        cudaFuncSetAttribute(tf32gemm<EPI_NONE>,      cudaFuncAttributeMaxDynamicSharedMemorySize, GEMM_SMEM_BYTES);
        cudaFuncSetAttribute(tf32gemm<EPI_BIAS>,      cudaFuncAttributeMaxDynamicSharedMemorySize, GEMM_SMEM_BYTES);
        cudaFuncSetAttribute(tf32gemm<EPI_BIAS_GELU>, cudaFuncAttributeMaxDynamicSharedMemorySize, GEMM_SMEM_BYTES);
        cudaFuncSetAttribute(tf32gemm<EPI_RES>,       cudaFuncAttributeMaxDynamicSharedMemorySize, GEMM_SMEM_BYTES);
        cudaFuncSetAttribute(tf32gemm<EPI_BIAS_RES>,  cudaFuncAttributeMaxDynamicSharedMemorySize, GEMM_SMEM_BYTES);
        attr_done = 1;
    }

    // 1) sc = silu(cond)
    silu_kernel<<<(T_TOK * 512 + 255) / 256, 256>>>(cond, sc, T_TOK * 512);

    // 2) gb1 = sc @ p1_w + p1_b   (4096x512 @ 512x2048)
    tf32gemm<EPI_BIAS><<<dim3(16, 32), 256, GEMM_SMEM_BYTES>>>(sc, p1_w, gb1, T_TOK, 2048, 512, p1_b, nullptr);

    // gb2 = sc @ p2_w + p2_b
    tf32gemm<EPI_BIAS><<<dim3(16, 32), 256, GEMM_SMEM_BYTES>>>(sc, p2_w, gb2, T_TOK, 2048, 512, p2_b, nullptr);

    // 3) h = adaln(x, gb1)
    adaln_kernel<<<T_TOK, 256>>>(x, gb1, h);

    // 4) qkv = h @ qkv_w  (4096x1024 @ 1024x3072)
    tf32gemm<EPI_NONE><<<dim3(24, 32), 256, GEMM_SMEM_BYTES>>>(h, qkv_w, qkvp, T_TOK, 3072, 1024, nullptr, nullptr);

    // 5) attention (tensor cores)
    attn_kernel<<<dim3(16, 32), 256, ATTN_SMEM_BYTES>>>(qkvp, attn);

    // 6) x2 = x + attn @ attn_out_w  (4096x1024 @ 1024x1024)
    tf32gemm<EPI_RES><<<dim3(8, 32), 256, GEMM_SMEM_BYTES>>>(attn, attn_o_w, x2, T_TOK, 1024, 1024, nullptr, x);

    // 7) h2 = adaln(x2, gb2)
    adaln_kernel<<<T_TOK, 256>>>(x2, gb2, h2);

    // 8) ff = gelu(h2 @ ffn_w1 + b1)  (4096x1024 @ 1024x4096)
    tf32gemm<EPI_BIAS_GELU><<<dim3(32, 32), 256, GEMM_SMEM_BYTES>>>(h2, ffn_w1, ff, T_TOK, 4096, 1024, ffn_b1, nullptr);

    // 9) out = x2 + ff @ ffn_w2 + b2  (4096x4096 @ 4096x1024)
    tf32gemm<EPI_BIAS_RES><<<dim3(8, 32), 256, GEMM_SMEM_BYTES>>>(ff, ffn_w2, out, T_TOK, 1024, 4096, ffn_b2, x2);
}